// round 7
// baseline (speedup 1.0000x reference)
#include <cuda_runtime.h>
#include <math.h>
#include <stdint.h>

// Problem constants
#define B_  2
#define L_  4096
#define D_  512
#define H_  8
#define HD_ 64
#define FF_ 2048
#define M_  (B_ * L_)          // 8192 rows
#define EPS_ 1e-5f

// ---------------- scratch (device globals; no allocation allowed) ----------
__device__ float g_q   [(size_t)M_ * D_];   // also reused for attn@Wo output
__device__ float g_k   [(size_t)M_ * D_];   // also reused for FFN2 output
__device__ float g_v   [(size_t)M_ * D_];
__device__ float g_attn[(size_t)M_ * D_];
__device__ float g_h   [(size_t)M_ * D_];
__device__ float g_ff1 [(size_t)M_ * FF_];

__device__ __forceinline__ void cp_async16(uint32_t smem_dst, const void* gptr) {
    asm volatile("cp.async.cg.shared.global [%0], [%1], 16;"
                 :: "r"(smem_dst), "l"(gptr));
}
__device__ __forceinline__ void cp_async_commit() {
    asm volatile("cp.async.commit_group;");
}
__device__ __forceinline__ void cp_async_wait_all() {
    asm volatile("cp.async.wait_group 0;");
}

// ---------------------------------------------------------------------------
// SGEMM core: C[M,N] = A[M,K] @ W[K,N] + bias (optional ReLU). Row-major all.
// BM=BN=128, BK=16, 256 threads, 8x8 micro-tile (4+4 split), double-buffered
// smem. B tiles arrive via cp.async; A tiles register-staged + transposed.
// One __syncthreads per K-step. Tile indices come from blockIdx.x/.y.
// ---------------------------------------------------------------------------
template <int N, int K, bool RELU>
__device__ __forceinline__ void sgemm_core(
    const float* __restrict__ A, const float* __restrict__ W,
    const float* __restrict__ bias, float* __restrict__ C)
{
    __shared__ float As[2][16][128];
    __shared__ float Bs[2][16][128];

    const int tid = threadIdx.x;
    const int bx = blockIdx.x;   // N tile
    const int by = blockIdx.y;   // M tile

    // A tile load: 128 rows x 16 cols = 512 float4 -> 256 threads x 2 float4
    const int arow = tid >> 1;            // 0..127
    const int acol = (tid & 1) * 8;       // 0 or 8
    // B tile load: 16 rows x 128 cols -> thread covers rows brow, brow+8
    const int brow = tid >> 5;            // 0..7
    const int bcol = (tid & 31) * 4;      // 0..124

    const int ty = tid >> 4;              // 0..15
    const int tx = tid & 15;              // 0..15

    float acc[8][8];
    #pragma unroll
    for (int i = 0; i < 8; i++)
        #pragma unroll
        for (int j = 0; j < 8; j++) acc[i][j] = 0.f;

    const float* Aptr = A + (size_t)(by * 128 + arow) * K + acol;
    const float* Bptr = W + (size_t)(bx * 128) + (size_t)brow * N + bcol;

    // smem byte addresses for this thread's two B destinations
    const uint32_t bs0 = (uint32_t)__cvta_generic_to_shared(&Bs[0][brow][bcol]);
    const uint32_t bs1 = (uint32_t)__cvta_generic_to_shared(&Bs[0][brow + 8][bcol]);
    const uint32_t bufStride = (uint32_t)(16 * 128 * sizeof(float)); // Bs[1]-Bs[0]

    constexpr int NT = K >> 4;   // number of BK=16 tiles (compile-time)

    // ---- prologue: tile 0 -> smem[0] ----
    {
        cp_async16(bs0, Bptr);
        cp_async16(bs1, Bptr + (size_t)8 * N);
        cp_async_commit();

        float4 a0 = *(const float4*)(Aptr);
        float4 a1 = *(const float4*)(Aptr + 4);
        As[0][acol + 0][arow] = a0.x;
        As[0][acol + 1][arow] = a0.y;
        As[0][acol + 2][arow] = a0.z;
        As[0][acol + 3][arow] = a0.w;
        As[0][acol + 4][arow] = a1.x;
        As[0][acol + 5][arow] = a1.y;
        As[0][acol + 6][arow] = a1.z;
        As[0][acol + 7][arow] = a1.w;
    }
    cp_async_wait_all();
    __syncthreads();

    for (int t = 0; t < NT; t++) {
        const int cur = t & 1;
        const int nxt = cur ^ 1;

        // async-copy next B tile into the other buffer (its last readers
        // passed the barrier at the end of iteration t-1)
        if (t + 1 < NT) {
            const float* bsrc = Bptr + (size_t)(t + 1) * 16 * N;
            cp_async16(bs0 + (uint32_t)nxt * bufStride, bsrc);
            cp_async16(bs1 + (uint32_t)nxt * bufStride, bsrc + (size_t)8 * N);
            cp_async_commit();
        }

        // prefetch next A tile into registers (overlaps with compute below)
        float4 pa0, pa1;
        if (t + 1 < NT) {
            pa0 = *(const float4*)(Aptr + (t + 1) * 16);
            pa1 = *(const float4*)(Aptr + (t + 1) * 16 + 4);
        }

        #pragma unroll
        for (int kk = 0; kk < 16; kk++) {
            float a[8], b[8];
            float4 a0 = *(const float4*)&As[cur][kk][ty * 4];
            float4 a1 = *(const float4*)&As[cur][kk][64 + ty * 4];
            a[0]=a0.x; a[1]=a0.y; a[2]=a0.z; a[3]=a0.w;
            a[4]=a1.x; a[5]=a1.y; a[6]=a1.z; a[7]=a1.w;
            float4 b0 = *(const float4*)&Bs[cur][kk][tx * 4];
            float4 b1 = *(const float4*)&Bs[cur][kk][64 + tx * 4];
            b[0]=b0.x; b[1]=b0.y; b[2]=b0.z; b[3]=b0.w;
            b[4]=b1.x; b[5]=b1.y; b[6]=b1.z; b[7]=b1.w;
            #pragma unroll
            for (int i = 0; i < 8; i++)
                #pragma unroll
                for (int j = 0; j < 8; j++)
                    acc[i][j] = fmaf(a[i], b[j], acc[i][j]);
        }

        if (t + 1 < NT) {
            As[nxt][acol + 0][arow] = pa0.x;
            As[nxt][acol + 1][arow] = pa0.y;
            As[nxt][acol + 2][arow] = pa0.z;
            As[nxt][acol + 3][arow] = pa0.w;
            As[nxt][acol + 4][arow] = pa1.x;
            As[nxt][acol + 5][arow] = pa1.y;
            As[nxt][acol + 6][arow] = pa1.z;
            As[nxt][acol + 7][arow] = pa1.w;
            cp_async_wait_all();
            __syncthreads();
        }
    }

    // Epilogue: bias (+ReLU), vectorized stores. Column groups tx*4 and 64+tx*4.
    const int cA = bx * 128 + tx * 4;
    const int cB = cA + 64;
    float4 biasA = *(const float4*)(bias + cA);
    float4 biasB = *(const float4*)(bias + cB);

    #pragma unroll
    for (int half = 0; half < 2; half++) {
        #pragma unroll
        for (int i = 0; i < 4; i++) {
            int row = by * 128 + half * 64 + ty * 4 + i;
            int ai = half * 4 + i;
            float4 vA, vB;
            vA.x = acc[ai][0] + biasA.x; vA.y = acc[ai][1] + biasA.y;
            vA.z = acc[ai][2] + biasA.z; vA.w = acc[ai][3] + biasA.w;
            vB.x = acc[ai][4] + biasB.x; vB.y = acc[ai][5] + biasB.y;
            vB.z = acc[ai][6] + biasB.z; vB.w = acc[ai][7] + biasB.w;
            if (RELU) {
                vA.x = fmaxf(vA.x, 0.f); vA.y = fmaxf(vA.y, 0.f);
                vA.z = fmaxf(vA.z, 0.f); vA.w = fmaxf(vA.w, 0.f);
                vB.x = fmaxf(vB.x, 0.f); vB.y = fmaxf(vB.y, 0.f);
                vB.z = fmaxf(vB.z, 0.f); vB.w = fmaxf(vB.w, 0.f);
            }
            *(float4*)(C + (size_t)row * N + cA) = vA;
            *(float4*)(C + (size_t)row * N + cB) = vB;
        }
    }
}

// single-GEMM wrapper (2 CTAs/SM guaranteed: caps regs at 128/thread)
template <int N, int K, bool RELU>
__global__ __launch_bounds__(256, 2) void sgemm_bias(
    const float* __restrict__ A, const float* __restrict__ W,
    const float* __restrict__ bias, float* __restrict__ C)
{
    sgemm_core<N, K, RELU>(A, W, bias, C);
}

// fused Q/K/V wrapper: blockIdx.z selects projection (uniform per block)
__global__ __launch_bounds__(256, 2) void sgemm_qkv3(
    const float* __restrict__ A,
    const float* __restrict__ Wq, const float* __restrict__ bq, float* __restrict__ Cq,
    const float* __restrict__ Wk, const float* __restrict__ bk, float* __restrict__ Ck,
    const float* __restrict__ Wv, const float* __restrict__ bv, float* __restrict__ Cv)
{
    const float* W; const float* bias; float* C;
    if (blockIdx.z == 0)      { W = Wq; bias = bq; C = Cq; }
    else if (blockIdx.z == 1) { W = Wk; bias = bk; C = Ck; }
    else                      { W = Wv; bias = bv; C = Cv; }
    sgemm_core<D_, D_, false>(A, W, bias, C);
}

// ---------------------------------------------------------------------------
// Banded attention, flash-style streaming softmax.
// Grid: (L/128, H, B); 128 threads, thread t owns query (qtile*128 + t).
// K/V processed in aligned chunks of 128 rows held in smem.
// ---------------------------------------------------------------------------
__global__ __launch_bounds__(128) void attn_kernel(
    const float* __restrict__ Q, const float* __restrict__ Kg,
    const float* __restrict__ Vg, float* __restrict__ O,
    const int* __restrict__ winp)
{
    __shared__ float Ks[128][HD_];
    __shared__ float Vs[128][HD_];

    const int w   = *winp;
    const int qt  = blockIdx.x;
    const int h   = blockIdx.y;
    const int b   = blockIdx.z;
    const int tid = threadIdx.x;
    const int qi  = qt * 128 + tid;
    const size_t baseBL = (size_t)b * L_;

    // load this thread's query row into registers, pre-scaled by 1/sqrt(HD)
    const float scale = rsqrtf((float)HD_);
    float q[HD_];
    const float* qrow = Q + (baseBL + qi) * D_ + h * HD_;
    #pragma unroll
    for (int i = 0; i < HD_ / 4; i++) {
        float4 v = *(const float4*)(qrow + i * 4);
        q[i*4+0] = v.x * scale; q[i*4+1] = v.y * scale;
        q[i*4+2] = v.z * scale; q[i*4+3] = v.w * scale;
    }

    float m = -INFINITY, l = 0.f;
    float acc[HD_];
    #pragma unroll
    for (int d = 0; d < HD_; d++) acc[d] = 0.f;

    int lo = qt * 128 - w; if (lo < 0) lo = 0;
    int hi = qt * 128 + 127 + w; if (hi > L_ - 1) hi = L_ - 1;
    const int c0 = lo >> 7, c1 = hi >> 7;

    for (int c = c0; c <= c1; c++) {
        const int k0 = c * 128;
        const float* kbase = Kg + (baseBL + k0) * D_ + h * HD_;
        const float* vbase = Vg + (baseBL + k0) * D_ + h * HD_;
        // cooperative chunk load: 128x64 floats = 2048 float4, 16 per thread
        #pragma unroll
        for (int it = 0; it < 16; it++) {
            int f = tid + it * 128;
            int r = f >> 4;
            int cc = (f & 15) * 4;
            *(float4*)&Ks[r][cc] = *(const float4*)(kbase + (size_t)r * D_ + cc);
            *(float4*)&Vs[r][cc] = *(const float4*)(vbase + (size_t)r * D_ + cc);
        }
        __syncthreads();

        int jlo = qi - w - k0; if (jlo < 0) jlo = 0;
        int jhi = qi + w - k0; if (jhi > 127) jhi = 127;
        for (int j = jlo; j <= jhi; j++) {
            float s = 0.f;
            #pragma unroll
            for (int d = 0; d < HD_; d++) s = fmaf(q[d], Ks[j][d], s);
            if (s > m) {
                float corr = __expf(m - s);
                m = s;
                l *= corr;
                #pragma unroll
                for (int d = 0; d < HD_; d++) acc[d] *= corr;
            }
            float p = __expf(s - m);
            l += p;
            #pragma unroll
            for (int d = 0; d < HD_; d++) acc[d] = fmaf(p, Vs[j][d], acc[d]);
        }
        __syncthreads();
    }

    const float inv = 1.f / l;
    float* orow = O + (baseBL + qi) * D_ + h * HD_;
    #pragma unroll
    for (int i = 0; i < HD_ / 4; i++) {
        float4 v;
        v.x = acc[i*4+0] * inv; v.y = acc[i*4+1] * inv;
        v.z = acc[i*4+2] * inv; v.w = acc[i*4+3] * inv;
        *(float4*)(orow + i * 4) = v;
    }
}

// ---------------------------------------------------------------------------
// out = LayerNorm(X + R) * g + b    (one block per row, 128 threads, D=512)
// ---------------------------------------------------------------------------
__global__ __launch_bounds__(128) void add_ln_kernel(
    const float* __restrict__ X, const float* __restrict__ R,
    const float* __restrict__ gamma, const float* __restrict__ beta,
    float* __restrict__ out)
{
    const int row = blockIdx.x;
    const int tid = threadIdx.x;
    const size_t off = (size_t)row * D_ + tid * 4;

    float4 xv = *(const float4*)(X + off);
    float4 rv = *(const float4*)(R + off);
    float v0 = xv.x + rv.x, v1 = xv.y + rv.y, v2 = xv.z + rv.z, v3 = xv.w + rv.w;

    float s  = v0 + v1 + v2 + v3;
    float s2 = v0*v0 + v1*v1 + v2*v2 + v3*v3;

    #pragma unroll
    for (int o = 16; o > 0; o >>= 1) {
        s  += __shfl_xor_sync(0xffffffffu, s,  o);
        s2 += __shfl_xor_sync(0xffffffffu, s2, o);
    }
    __shared__ float sh[8];
    const int warp = tid >> 5;
    if ((tid & 31) == 0) { sh[warp] = s; sh[warp + 4] = s2; }
    __syncthreads();
    s  = sh[0] + sh[1] + sh[2] + sh[3];
    s2 = sh[4] + sh[5] + sh[6] + sh[7];

    const float mean = s * (1.f / D_);
    const float var  = s2 * (1.f / D_) - mean * mean;
    const float rstd = rsqrtf(var + EPS_);

    float4 gv = *(const float4*)(gamma + tid * 4);
    float4 bv = *(const float4*)(beta  + tid * 4);
    float4 ov;
    ov.x = (v0 - mean) * rstd * gv.x + bv.x;
    ov.y = (v1 - mean) * rstd * gv.y + bv.y;
    ov.z = (v2 - mean) * rstd * gv.z + bv.z;
    ov.w = (v3 - mean) * rstd * gv.w + bv.w;
    *(float4*)(out + off) = ov;
}

// ---------------------------------------------------------------------------
extern "C" void kernel_launch(void* const* d_in, const int* in_sizes, int n_in,
                              void* d_out, int out_size)
{
    const float* x     = (const float*)d_in[0];
    const float* Wq    = (const float*)d_in[1];
    const float* bq    = (const float*)d_in[2];
    const float* Wk    = (const float*)d_in[3];
    const float* bk    = (const float*)d_in[4];
    const float* Wv    = (const float*)d_in[5];
    const float* bv    = (const float*)d_in[6];
    const float* Wo    = (const float*)d_in[7];
    const float* bo    = (const float*)d_in[8];
    const float* ln1g  = (const float*)d_in[9];
    const float* ln1b  = (const float*)d_in[10];
    const float* W1    = (const float*)d_in[11];
    const float* b1    = (const float*)d_in[12];
    const float* W2    = (const float*)d_in[13];
    const float* b2    = (const float*)d_in[14];
    const float* ln2g  = (const float*)d_in[15];
    const float* ln2b  = (const float*)d_in[16];
    const int*   win   = (const int*)  d_in[17];

    float *pq, *pk, *pv, *pattn, *ph, *pff1;
    cudaGetSymbolAddress((void**)&pq,    g_q);
    cudaGetSymbolAddress((void**)&pk,    g_k);
    cudaGetSymbolAddress((void**)&pv,    g_v);
    cudaGetSymbolAddress((void**)&pattn, g_attn);
    cudaGetSymbolAddress((void**)&ph,    g_h);
    cudaGetSymbolAddress((void**)&pff1,  g_ff1);

    float* out = (float*)d_out;

    dim3 gemmBlk(256);
    dim3 gridD(D_ / 128, M_ / 128);        // N=512 tiles
    dim3 gridQKV(D_ / 128, M_ / 128, 3);   // fused Q/K/V
    dim3 gridFF(FF_ / 128, M_ / 128);      // N=2048 tiles

    // Q, K, V projections (single fused launch)
    sgemm_qkv3<<<gridQKV, gemmBlk>>>(x, Wq, bq, pq, Wk, bk, pk, Wv, bv, pv);

    // banded attention
    dim3 agrid(L_ / 128, H_, B_);
    attn_kernel<<<agrid, 128>>>(pq, pk, pv, pattn, win);

    // output projection (reuse g_q; attn no longer needs q)
    sgemm_bias<D_, D_, false><<<gridD, gemmBlk>>>(pattn, Wo, bo, pq);

    // h = LN(x + attn_out)
    add_ln_kernel<<<M_, 128>>>(x, pq, ln1g, ln1b, ph);

    // FFN
    sgemm_bias<FF_, D_, true><<<gridFF, gemmBlk>>>(ph, W1, b1, pff1);
    sgemm_bias<D_, FF_, false><<<gridD, gemmBlk>>>(pff1, W2, b2, pk);

    // out = LN(h + ffn_out)
    add_ln_kernel<<<M_, 128>>>(ph, pk, ln2g, ln2b, out);
}

// round 13
// speedup vs baseline: 1.4071x; 1.4071x over previous
#include <cuda_runtime.h>
#include <math.h>
#include <stdint.h>

// Problem constants
#define B_  2
#define L_  4096
#define D_  512
#define H_  8
#define HD_ 64
#define FF_ 2048
#define M_  (B_ * L_)          // 8192 rows
#define EPS_ 1e-5f

// ---------------- scratch (device globals; no allocation allowed) ----------
__device__ float g_q   [(size_t)M_ * D_];   // also reused for attn@Wo output
__device__ float g_k   [(size_t)M_ * D_];   // also reused for FFN2 output
__device__ float g_v   [(size_t)M_ * D_];
__device__ float g_attn[(size_t)M_ * D_];
__device__ float g_h   [(size_t)M_ * D_];
__device__ float g_ff1 [(size_t)M_ * FF_];

__device__ __forceinline__ void cp_async16(uint32_t smem_dst, const void* gptr) {
    asm volatile("cp.async.cg.shared.global [%0], [%1], 16;"
                 :: "r"(smem_dst), "l"(gptr));
}
__device__ __forceinline__ void cp_async_commit() {
    asm volatile("cp.async.commit_group;");
}
__device__ __forceinline__ void cp_async_wait_all() {
    asm volatile("cp.async.wait_group 0;");
}
__device__ __forceinline__ unsigned f2tf32(float f) {
    unsigned u;
    asm("cvt.rna.tf32.f32 %0, %1;" : "=r"(u) : "f"(f));
    return u;
}
__device__ __forceinline__ void mma_tf32(
    float& d0, float& d1, float& d2, float& d3,
    unsigned a0, unsigned a1, unsigned a2, unsigned a3,
    unsigned b0, unsigned b1)
{
    asm volatile(
        "mma.sync.aligned.m16n8k8.row.col.f32.tf32.tf32.f32 "
        "{%0,%1,%2,%3}, {%4,%5,%6,%7}, {%8,%9}, {%0,%1,%2,%3};\n"
        : "+f"(d0), "+f"(d1), "+f"(d2), "+f"(d3)
        : "r"(a0), "r"(a1), "r"(a2), "r"(a3), "r"(b0), "r"(b1));
}

// ---------------------------------------------------------------------------
// TF32 tensor-core GEMM: C[M,N] = A[M,K] @ W[K,N] + bias (optional ReLU).
// BM=BN=128, BK=16, 256 threads (8 warps), warp tile 64x32 (4x4 m16n8k8
// atoms), double-buffered smem with pitch 136 floats (bank-conflict-free
// fragment loads: bank = (8q + g) % 32, a permutation).
// A is tf32-converted at STS; B arrives fp32 via cp.async, converted at
// fragment load. fp32 accumulate.
// ---------------------------------------------------------------------------
#define PITCH_ 136
#define STAGEW_ (16 * PITCH_)

template <int N, int K, bool RELU>
__device__ __forceinline__ void sgemm_core_tf32(
    const float* __restrict__ A, const float* __restrict__ W,
    const float* __restrict__ bias, float* __restrict__ C)
{
    __shared__ unsigned As[2][STAGEW_];
    __shared__ float    Bs[2][STAGEW_];

    const int tid  = threadIdx.x;
    const int lane = tid & 31;
    const int warp = tid >> 5;
    const int g = lane >> 2;      // groupID (0..7)
    const int q = lane & 3;       // threadID-in-group (0..3)

    const int bx = blockIdx.x;    // N tile
    const int by = blockIdx.y;    // M tile

    const int warp_m = warp & 1;  // 0..1 -> 64 rows each
    const int warp_n = warp >> 1; // 0..3 -> 32 cols each
    const int m_w = warp_m * 64;
    const int n_w = warp_n * 32;

    // A gmem load mapping: 128 rows x 16 cols -> 256 threads x 2 float4
    const int arow = tid >> 1;           // 0..127
    const int acol = (tid & 1) * 8;      // 0 or 8
    // B cp.async mapping: 16 rows x 128 cols -> rows brow, brow+8
    const int brow = tid >> 5;           // 0..7
    const int bcol = (tid & 31) * 4;     // 0..124

    float acc[4][4][4];   // [m-atom][n-atom][reg]
    #pragma unroll
    for (int i = 0; i < 4; i++)
        #pragma unroll
        for (int t2 = 0; t2 < 4; t2++)
            #pragma unroll
            for (int r = 0; r < 4; r++) acc[i][t2][r] = 0.f;

    const float* Aptr = A + (size_t)(by * 128 + arow) * K + acol;
    const float* Bptr = W + (size_t)(bx * 128) + (size_t)brow * N + bcol;

    const uint32_t bsm0 = (uint32_t)__cvta_generic_to_shared(&Bs[0][0]);
    const uint32_t boff0 = (uint32_t)((brow * PITCH_ + bcol) * 4);
    const uint32_t boff1 = (uint32_t)(((brow + 8) * PITCH_ + bcol) * 4);
    const uint32_t stageBytes = (uint32_t)(STAGEW_ * 4);

    constexpr int NT = K >> 4;

    // ---- prologue: tile 0 -> stage 0 ----
    {
        cp_async16(bsm0 + boff0, Bptr);
        cp_async16(bsm0 + boff1, Bptr + (size_t)8 * N);
        cp_async_commit();

        float4 a0 = *(const float4*)(Aptr);
        float4 a1 = *(const float4*)(Aptr + 4);
        unsigned* Ad = As[0];
        Ad[(acol + 0) * PITCH_ + arow] = f2tf32(a0.x);
        Ad[(acol + 1) * PITCH_ + arow] = f2tf32(a0.y);
        Ad[(acol + 2) * PITCH_ + arow] = f2tf32(a0.z);
        Ad[(acol + 3) * PITCH_ + arow] = f2tf32(a0.w);
        Ad[(acol + 4) * PITCH_ + arow] = f2tf32(a1.x);
        Ad[(acol + 5) * PITCH_ + arow] = f2tf32(a1.y);
        Ad[(acol + 6) * PITCH_ + arow] = f2tf32(a1.z);
        Ad[(acol + 7) * PITCH_ + arow] = f2tf32(a1.w);
    }
    cp_async_wait_all();
    __syncthreads();

    for (int t = 0; t < NT; t++) {
        const int cur = t & 1;
        const int nxt = cur ^ 1;

        // async-copy next B tile (buffer's readers retired at prior barrier)
        if (t + 1 < NT) {
            const float* bsrc = Bptr + (size_t)(t + 1) * 16 * N;
            cp_async16(bsm0 + (uint32_t)nxt * stageBytes + boff0, bsrc);
            cp_async16(bsm0 + (uint32_t)nxt * stageBytes + boff1, bsrc + (size_t)8 * N);
            cp_async_commit();
        }

        // prefetch next A tile into registers
        float4 pa0, pa1;
        if (t + 1 < NT) {
            pa0 = *(const float4*)(Aptr + (t + 1) * 16);
            pa1 = *(const float4*)(Aptr + (t + 1) * 16 + 4);
        }

        // ---- tensor-core compute on current stage ----
        {
            const unsigned* Ac = As[cur];
            const float*    Bc = Bs[cur];
            #pragma unroll
            for (int j = 0; j < 2; j++) {
                const int k0 = j * 8 + q;
                unsigned af[4][4];
                #pragma unroll
                for (int i = 0; i < 4; i++) {
                    const int mb = m_w + i * 16 + g;
                    af[i][0] = Ac[k0 * PITCH_ + mb];
                    af[i][1] = Ac[k0 * PITCH_ + mb + 8];
                    af[i][2] = Ac[(k0 + 4) * PITCH_ + mb];
                    af[i][3] = Ac[(k0 + 4) * PITCH_ + mb + 8];
                }
                unsigned bf[4][2];
                #pragma unroll
                for (int t2 = 0; t2 < 4; t2++) {
                    const int nb = n_w + t2 * 8 + g;
                    bf[t2][0] = f2tf32(Bc[k0 * PITCH_ + nb]);
                    bf[t2][1] = f2tf32(Bc[(k0 + 4) * PITCH_ + nb]);
                }
                #pragma unroll
                for (int i = 0; i < 4; i++)
                    #pragma unroll
                    for (int t2 = 0; t2 < 4; t2++)
                        mma_tf32(acc[i][t2][0], acc[i][t2][1],
                                 acc[i][t2][2], acc[i][t2][3],
                                 af[i][0], af[i][1], af[i][2], af[i][3],
                                 bf[t2][0], bf[t2][1]);
            }
        }

        if (t + 1 < NT) {
            unsigned* Ad = As[nxt];
            Ad[(acol + 0) * PITCH_ + arow] = f2tf32(pa0.x);
            Ad[(acol + 1) * PITCH_ + arow] = f2tf32(pa0.y);
            Ad[(acol + 2) * PITCH_ + arow] = f2tf32(pa0.z);
            Ad[(acol + 3) * PITCH_ + arow] = f2tf32(pa0.w);
            Ad[(acol + 4) * PITCH_ + arow] = f2tf32(pa1.x);
            Ad[(acol + 5) * PITCH_ + arow] = f2tf32(pa1.y);
            Ad[(acol + 6) * PITCH_ + arow] = f2tf32(pa1.z);
            Ad[(acol + 7) * PITCH_ + arow] = f2tf32(pa1.w);
            cp_async_wait_all();
            __syncthreads();
        }
    }

    // ---- epilogue: bias (+ReLU), float2 stores per fragment ----
    #pragma unroll
    for (int i = 0; i < 4; i++) {
        const int r0 = by * 128 + m_w + i * 16 + g;
        #pragma unroll
        for (int t2 = 0; t2 < 4; t2++) {
            const int col = bx * 128 + n_w + t2 * 8 + 2 * q;
            float2 bv = *(const float2*)(bias + col);
            float v0 = acc[i][t2][0] + bv.x;
            float v1 = acc[i][t2][1] + bv.y;
            float v2 = acc[i][t2][2] + bv.x;
            float v3 = acc[i][t2][3] + bv.y;
            if (RELU) {
                v0 = fmaxf(v0, 0.f); v1 = fmaxf(v1, 0.f);
                v2 = fmaxf(v2, 0.f); v3 = fmaxf(v3, 0.f);
            }
            *(float2*)(C + (size_t)r0 * N + col)       = make_float2(v0, v1);
            *(float2*)(C + (size_t)(r0 + 8) * N + col) = make_float2(v2, v3);
        }
    }
}

// single-GEMM wrapper (2 CTAs/SM guaranteed: caps regs at 128/thread)
template <int N, int K, bool RELU>
__global__ __launch_bounds__(256, 2) void sgemm_bias(
    const float* __restrict__ A, const float* __restrict__ W,
    const float* __restrict__ bias, float* __restrict__ C)
{
    sgemm_core_tf32<N, K, RELU>(A, W, bias, C);
}

// fused Q/K/V wrapper: blockIdx.z selects projection (uniform per block)
__global__ __launch_bounds__(256, 2) void sgemm_qkv3(
    const float* __restrict__ A,
    const float* __restrict__ Wq, const float* __restrict__ bq, float* __restrict__ Cq,
    const float* __restrict__ Wk, const float* __restrict__ bk, float* __restrict__ Ck,
    const float* __restrict__ Wv, const float* __restrict__ bv, float* __restrict__ Cv)
{
    const float* W; const float* bias; float* C;
    if (blockIdx.z == 0)      { W = Wq; bias = bq; C = Cq; }
    else if (blockIdx.z == 1) { W = Wk; bias = bk; C = Ck; }
    else                      { W = Wv; bias = bv; C = Cv; }
    sgemm_core_tf32<D_, D_, false>(A, W, bias, C);
}

// ---------------------------------------------------------------------------
// Banded attention, flash-style streaming softmax (full fp32).
// Grid: (L/128, H, B); 128 threads, thread t owns query (qtile*128 + t).
// ---------------------------------------------------------------------------
__global__ __launch_bounds__(128) void attn_kernel(
    const float* __restrict__ Q, const float* __restrict__ Kg,
    const float* __restrict__ Vg, float* __restrict__ O,
    const int* __restrict__ winp)
{
    __shared__ float Ks[128][HD_];
    __shared__ float Vs[128][HD_];

    const int w   = *winp;
    const int qt  = blockIdx.x;
    const int h   = blockIdx.y;
    const int b   = blockIdx.z;
    const int tid = threadIdx.x;
    const int qi  = qt * 128 + tid;
    const size_t baseBL = (size_t)b * L_;

    // load this thread's query row into registers, pre-scaled by 1/sqrt(HD)
    const float scale = rsqrtf((float)HD_);
    float q[HD_];
    const float* qrow = Q + (baseBL + qi) * D_ + h * HD_;
    #pragma unroll
    for (int i = 0; i < HD_ / 4; i++) {
        float4 v = *(const float4*)(qrow + i * 4);
        q[i*4+0] = v.x * scale; q[i*4+1] = v.y * scale;
        q[i*4+2] = v.z * scale; q[i*4+3] = v.w * scale;
    }

    float m = -INFINITY, l = 0.f;
    float acc[HD_];
    #pragma unroll
    for (int d = 0; d < HD_; d++) acc[d] = 0.f;

    int lo = qt * 128 - w; if (lo < 0) lo = 0;
    int hi = qt * 128 + 127 + w; if (hi > L_ - 1) hi = L_ - 1;
    const int c0 = lo >> 7, c1 = hi >> 7;

    for (int c = c0; c <= c1; c++) {
        const int k0 = c * 128;
        const float* kbase = Kg + (baseBL + k0) * D_ + h * HD_;
        const float* vbase = Vg + (baseBL + k0) * D_ + h * HD_;
        #pragma unroll
        for (int it = 0; it < 16; it++) {
            int f = tid + it * 128;
            int r = f >> 4;
            int cc = (f & 15) * 4;
            *(float4*)&Ks[r][cc] = *(const float4*)(kbase + (size_t)r * D_ + cc);
            *(float4*)&Vs[r][cc] = *(const float4*)(vbase + (size_t)r * D_ + cc);
        }
        __syncthreads();

        int jlo = qi - w - k0; if (jlo < 0) jlo = 0;
        int jhi = qi + w - k0; if (jhi > 127) jhi = 127;
        for (int j = jlo; j <= jhi; j++) {
            float s = 0.f;
            #pragma unroll
            for (int d = 0; d < HD_; d++) s = fmaf(q[d], Ks[j][d], s);
            if (s > m) {
                float corr = __expf(m - s);
                m = s;
                l *= corr;
                #pragma unroll
                for (int d = 0; d < HD_; d++) acc[d] *= corr;
            }
            float p = __expf(s - m);
            l += p;
            #pragma unroll
            for (int d = 0; d < HD_; d++) acc[d] = fmaf(p, Vs[j][d], acc[d]);
        }
        __syncthreads();
    }

    const float inv = 1.f / l;
    float* orow = O + (baseBL + qi) * D_ + h * HD_;
    #pragma unroll
    for (int i = 0; i < HD_ / 4; i++) {
        float4 v;
        v.x = acc[i*4+0] * inv; v.y = acc[i*4+1] * inv;
        v.z = acc[i*4+2] * inv; v.w = acc[i*4+3] * inv;
        *(float4*)(orow + i * 4) = v;
    }
}

// ---------------------------------------------------------------------------
// out = LayerNorm(X + R) * g + b    (one block per row, 128 threads, D=512)
// ---------------------------------------------------------------------------
__global__ __launch_bounds__(128) void add_ln_kernel(
    const float* __restrict__ X, const float* __restrict__ R,
    const float* __restrict__ gamma, const float* __restrict__ beta,
    float* __restrict__ out)
{
    const int row = blockIdx.x;
    const int tid = threadIdx.x;
    const size_t off = (size_t)row * D_ + tid * 4;

    float4 xv = *(const float4*)(X + off);
    float4 rv = *(const float4*)(R + off);
    float v0 = xv.x + rv.x, v1 = xv.y + rv.y, v2 = xv.z + rv.z, v3 = xv.w + rv.w;

    float s  = v0 + v1 + v2 + v3;
    float s2 = v0*v0 + v1*v1 + v2*v2 + v3*v3;

    #pragma unroll
    for (int o = 16; o > 0; o >>= 1) {
        s  += __shfl_xor_sync(0xffffffffu, s,  o);
        s2 += __shfl_xor_sync(0xffffffffu, s2, o);
    }
    __shared__ float sh[8];
    const int warp = tid >> 5;
    if ((tid & 31) == 0) { sh[warp] = s; sh[warp + 4] = s2; }
    __syncthreads();
    s  = sh[0] + sh[1] + sh[2] + sh[3];
    s2 = sh[4] + sh[5] + sh[6] + sh[7];

    const float mean = s * (1.f / D_);
    const float var  = s2 * (1.f / D_) - mean * mean;
    const float rstd = rsqrtf(var + EPS_);

    float4 gv = *(const float4*)(gamma + tid * 4);
    float4 bv = *(const float4*)(beta  + tid * 4);
    float4 ov;
    ov.x = (v0 - mean) * rstd * gv.x + bv.x;
    ov.y = (v1 - mean) * rstd * gv.y + bv.y;
    ov.z = (v2 - mean) * rstd * gv.z + bv.z;
    ov.w = (v3 - mean) * rstd * gv.w + bv.w;
    *(float4*)(out + off) = ov;
}

// ---------------------------------------------------------------------------
extern "C" void kernel_launch(void* const* d_in, const int* in_sizes, int n_in,
                              void* d_out, int out_size)
{
    const float* x     = (const float*)d_in[0];
    const float* Wq    = (const float*)d_in[1];
    const float* bq    = (const float*)d_in[2];
    const float* Wk    = (const float*)d_in[3];
    const float* bk    = (const float*)d_in[4];
    const float* Wv    = (const float*)d_in[5];
    const float* bv    = (const float*)d_in[6];
    const float* Wo    = (const float*)d_in[7];
    const float* bo    = (const float*)d_in[8];
    const float* ln1g  = (const float*)d_in[9];
    const float* ln1b  = (const float*)d_in[10];
    const float* W1    = (const float*)d_in[11];
    const float* b1    = (const float*)d_in[12];
    const float* W2    = (const float*)d_in[13];
    const float* b2    = (const float*)d_in[14];
    const float* ln2g  = (const float*)d_in[15];
    const float* ln2b  = (const float*)d_in[16];
    const int*   win   = (const int*)  d_in[17];

    float *pq, *pk, *pv, *pattn, *ph, *pff1;
    cudaGetSymbolAddress((void**)&pq,    g_q);
    cudaGetSymbolAddress((void**)&pk,    g_k);
    cudaGetSymbolAddress((void**)&pv,    g_v);
    cudaGetSymbolAddress((void**)&pattn, g_attn);
    cudaGetSymbolAddress((void**)&ph,    g_h);
    cudaGetSymbolAddress((void**)&pff1,  g_ff1);

    float* out = (float*)d_out;

    dim3 gemmBlk(256);
    dim3 gridD(D_ / 128, M_ / 128);        // N=512 tiles
    dim3 gridQKV(D_ / 128, M_ / 128, 3);   // fused Q/K/V
    dim3 gridFF(FF_ / 128, M_ / 128);      // N=2048 tiles

    // Q, K, V projections (single fused launch, tf32 tensor cores)
    sgemm_qkv3<<<gridQKV, gemmBlk>>>(x, Wq, bq, pq, Wk, bk, pk, Wv, bv, pv);

    // banded attention (fp32)
    dim3 agrid(L_ / 128, H_, B_);
    attn_kernel<<<agrid, 128>>>(pq, pk, pv, pattn, win);

    // output projection (reuse g_q; attn no longer needs q)
    sgemm_bias<D_, D_, false><<<gridD, gemmBlk>>>(pattn, Wo, bo, pq);

    // h = LN(x + attn_out)
    add_ln_kernel<<<M_, 128>>>(x, pq, ln1g, ln1b, ph);

    // FFN
    sgemm_bias<FF_, D_, true><<<gridFF, gemmBlk>>>(ph, W1, b1, pff1);
    sgemm_bias<D_, FF_, false><<<gridD, gemmBlk>>>(pff1, W2, b2, pk);

    // out = LN(h + ffn_out)
    add_ln_kernel<<<M_, 128>>>(ph, pk, ln2g, ln2b, out);
}